// round 2
// baseline (speedup 1.0000x reference)
#include <cuda_runtime.h>
#include <cuda_fp16.h>
#include <cstdint>

#define NT        4096      // M / 128 tiles
#define GRIDSZ    148
#define THREADS   512
#define BM        128
#define KDIM      256
#define NDIM      256

// ---- dynamic smem layout (bytes) ----
#define OFF_C     0                    // 256 fp32 (bias - subtract)
#define OFF_PMAX  1024                 // 4 x 128 fp32
#define OFF_PSUM  3072                 // 4 x 128 fp32
#define OFF_G     5120                 // 128 fp32
#define OFF_A     6144                 // 128 x 256 fp16 = 65536 (1024-aligned)
#define OFF_B     71680                // 256 x 256 fp16 = 131072
#define SMEM_TOTAL 202752

__device__ __forceinline__ uint32_t cvta_smem(const void* p) {
    uint32_t a;
    asm("{ .reg .u64 t; cvta.to.shared.u64 t, %1; cvt.u32.u64 %0, t; }" : "=r"(a) : "l"(p));
    return a;
}

// Swizzle<3,3,3>: row stride 512B (256 fp16). chunk(16B) index ^= row&7.
__device__ __forceinline__ uint32_t sw_off(int row, int col) {
    return (uint32_t)(row * 512 + (((col >> 3) ^ (row & 7)) << 4) + (col & 7) * 2);
}

#define LDSM_X4(r0, r1, r2, r3, addr) \
    asm volatile("ldmatrix.sync.aligned.m8n8.x4.shared.b16 {%0,%1,%2,%3}, [%4];" \
                 : "=r"(r0), "=r"(r1), "=r"(r2), "=r"(r3) : "r"(addr))

#define MMA16816(d, a, b0, b1) \
    asm volatile("mma.sync.aligned.m16n8k16.row.col.f32.f16.f16.f32 " \
                 "{%0,%1,%2,%3}, {%4,%5,%6,%7}, {%8,%9}, {%0,%1,%2,%3};" \
                 : "+f"((d)[0]), "+f"((d)[1]), "+f"((d)[2]), "+f"((d)[3]) \
                 : "r"((a)[0]), "r"((a)[1]), "r"((a)[2]), "r"((a)[3]), \
                   "r"(b0), "r"(b1))

__global__ void __launch_bounds__(THREADS, 1)
fused_gemm_lse_gelu_kernel(const float* __restrict__ x,
                           const float* __restrict__ w,
                           const float* __restrict__ bias,
                           const float* __restrict__ sub,
                           float* __restrict__ out) {
    extern __shared__ char sm[];
    const uint32_t sb = cvta_smem(sm);
    const int tid = threadIdx.x;
    const int wid = tid >> 5;
    const int lane = tid & 31;
    const int mw = wid & 3;        // M-group: rows mw*32 .. +31
    const int nw = wid >> 2;       // N-group: cols nw*64 .. +63

    float* csh  = (float*)(sm + OFF_C);
    float* pmax = (float*)(sm + OFF_PMAX);
    float* psum = (float*)(sm + OFF_PSUM);
    float* gsh  = (float*)(sm + OFF_G);

    // ---- stage W fp32 -> fp16 swizzled SMEM (resident whole kernel) ----
    {
        const float4* wp = (const float4*)w;
#pragma unroll
        for (int i = 0; i < 32; i++) {
            int e = i * 2048 + tid * 4;
            float4 v = wp[i * 512 + tid];
            int n = e >> 8, k = e & 255;
            __half2 p0 = __floats2half2_rn(v.x, v.y);
            __half2 p1 = __floats2half2_rn(v.z, v.w);
            uint32_t addr = sb + OFF_B + sw_off(n, k);
            asm volatile("st.shared.v2.b32 [%0], {%1,%2};"
                         :: "r"(addr), "r"(*(uint32_t*)&p0), "r"(*(uint32_t*)&p1));
        }
    }
    if (tid < 256) csh[tid] = bias[tid] - sub[tid];

    const int t0 = blockIdx.x;
    uint32_t h2[32];

    // ---- stage first tile's A ----
    {
        const float4* xp = (const float4*)(x + (size_t)t0 * (BM * KDIM));
#pragma unroll
        for (int i = 0; i < 16; i++) {
            float4 v = __ldcs(xp + i * 512 + tid);
            __half2 a = __floats2half2_rn(v.x, v.y);
            __half2 b = __floats2half2_rn(v.z, v.w);
            h2[2 * i] = *(uint32_t*)&a;
            h2[2 * i + 1] = *(uint32_t*)&b;
        }
#pragma unroll
        for (int i = 0; i < 16; i++) {
            int e = i * 2048 + tid * 4;
            uint32_t addr = sb + OFF_A + sw_off(e >> 8, e & 255);
            asm volatile("st.shared.v2.b32 [%0], {%1,%2};"
                         :: "r"(addr), "r"(h2[2 * i]), "r"(h2[2 * i + 1]));
        }
    }

    // ---- precompute ldmatrix lane addresses (k-invariant parts) ----
    const int t4 = lane >> 3;                 // matrix index 0..3
    // A: row = mw*32 + mb*16 + (t4&1)*8 + (lane&7); k-half = t4>>1
    const int a_row0 = mw * 32 + (t4 & 1) * 8 + (lane & 7);
    const int a_kh   = t4 >> 1;               // 0 or 1 (k offset 0/8)
    // B: n = nw*64 + ng*16 + (t4>>1)*8 + (lane&7); k-half = t4&1
    const int b_row0 = nw * 64 + (t4 >> 1) * 8 + (lane & 7);
    const int b_kh   = t4 & 1;

    const uint32_t aBase0 = sb + OFF_A + (uint32_t)(a_row0 * 512);
    const uint32_t aBase1 = sb + OFF_A + (uint32_t)((a_row0 + 16) * 512);
    const uint32_t aRx = (uint32_t)(a_row0 & 7);
    uint32_t bBase[4], bRx[4];
#pragma unroll
    for (int ng = 0; ng < 4; ng++) {
        int br = b_row0 + ng * 16;
        bBase[ng] = sb + OFF_B + (uint32_t)(br * 512);
        bRx[ng] = (uint32_t)(br & 7);
    }

    for (int t = t0; t < NT; t += GRIDSZ) {
        __syncthreads();  // A(t) + B visible

        float acc[64];
#pragma unroll
        for (int i = 0; i < 64; i++) acc[i] = 0.0f;

        // ---- MMA mainloop: 16 k-steps of k16 ----
#pragma unroll
        for (int ks = 0; ks < 16; ks++) {
            const uint32_t kc = (uint32_t)(2 * ks);   // 16B-chunk index of k0
            uint32_t a0[4], a1[4];
            LDSM_X4(a0[0], a0[1], a0[2], a0[3], aBase0 + (((kc + a_kh) ^ aRx) << 4));
            LDSM_X4(a1[0], a1[1], a1[2], a1[3], aBase1 + (((kc + a_kh) ^ aRx) << 4));
            uint32_t bf[4][4];
#pragma unroll
            for (int ng = 0; ng < 4; ng++)
                LDSM_X4(bf[ng][0], bf[ng][1], bf[ng][2], bf[ng][3],
                        bBase[ng] + (((kc + b_kh) ^ bRx[ng]) << 4));
#pragma unroll
            for (int ng = 0; ng < 4; ng++) {
                MMA16816(&acc[(0 * 8 + ng * 2 + 0) * 4], a0, bf[ng][0], bf[ng][1]);
                MMA16816(&acc[(0 * 8 + ng * 2 + 1) * 4], a0, bf[ng][2], bf[ng][3]);
                MMA16816(&acc[(1 * 8 + ng * 2 + 0) * 4], a1, bf[ng][0], bf[ng][1]);
                MMA16816(&acc[(1 * 8 + ng * 2 + 1) * 4], a1, bf[ng][2], bf[ng][3]);
            }
        }

        // ---- prefetch next tile's x (drains under epilogue) ----
        const int tn = t + GRIDSZ;
        const bool hn = tn < NT;
        if (hn) {
            const float4* xp = (const float4*)(x + (size_t)tn * (BM * KDIM));
#pragma unroll
            for (int i = 0; i < 16; i++) {
                float4 v = __ldcs(xp + i * 512 + tid);
                __half2 a = __floats2half2_rn(v.x, v.y);
                __half2 b = __floats2half2_rn(v.z, v.w);
                h2[2 * i] = *(uint32_t*)&a;
                h2[2 * i + 1] = *(uint32_t*)&b;
            }
        }

        // ---- epilogue: per-row max & sum over this warp's 64 cols ----
        {
            const int n0 = nw * 64;
            float m4[4] = {-3.0e38f, -3.0e38f, -3.0e38f, -3.0e38f};
            float s4[4] = {0.0f, 0.0f, 0.0f, 0.0f};
#pragma unroll
            for (int nt = 0; nt < 8; nt++) {
                float c0 = csh[n0 + nt * 8 + (lane & 3) * 2];
                float c1 = csh[n0 + nt * 8 + (lane & 3) * 2 + 1];
#pragma unroll
                for (int mb = 0; mb < 2; mb++) {
                    const float* a = &acc[(mb * 8 + nt) * 4];
                    m4[2 * mb + 0] = fmaxf(m4[2 * mb + 0], fmaxf(a[0] + c0, a[1] + c1));
                    m4[2 * mb + 1] = fmaxf(m4[2 * mb + 1], fmaxf(a[2] + c0, a[3] + c1));
                }
            }
#pragma unroll
            for (int nt = 0; nt < 8; nt++) {
                float c0 = csh[n0 + nt * 8 + (lane & 3) * 2];
                float c1 = csh[n0 + nt * 8 + (lane & 3) * 2 + 1];
#pragma unroll
                for (int mb = 0; mb < 2; mb++) {
                    const float* a = &acc[(mb * 8 + nt) * 4];
                    s4[2 * mb + 0] += __expf(a[0] + c0 - m4[2 * mb + 0])
                                    + __expf(a[1] + c1 - m4[2 * mb + 0]);
                    s4[2 * mb + 1] += __expf(a[2] + c0 - m4[2 * mb + 1])
                                    + __expf(a[3] + c1 - m4[2 * mb + 1]);
                }
            }
            // butterfly over the 4 lanes sharing a row (lane%4 group)
#pragma unroll
            for (int off = 1; off <= 2; off <<= 1) {
#pragma unroll
                for (int j = 0; j < 4; j++) {
                    float m2 = __shfl_xor_sync(0xFFFFFFFFu, m4[j], off);
                    float s2 = __shfl_xor_sync(0xFFFFFFFFu, s4[j], off);
                    float nm = fmaxf(m4[j], m2);
                    s4[j] = s4[j] * __expf(m4[j] - nm) + s2 * __expf(m2 - nm);
                    m4[j] = nm;
                }
            }
            if ((lane & 3) == 0) {
#pragma unroll
                for (int j = 0; j < 4; j++) {
                    int row = mw * 32 + (j >> 1) * 16 + (j & 1) * 8 + (lane >> 2);
                    pmax[nw * 128 + row] = m4[j];
                    psum[nw * 128 + row] = s4[j];
                }
            }
        }
        __syncthreads();

        // ---- combine 4 N-group partials -> lse -> gelu ----
        if (tid < 128) {
            float m0 = pmax[tid], m1 = pmax[128 + tid], m2 = pmax[256 + tid], m3 = pmax[384 + tid];
            float M = fmaxf(fmaxf(m0, m1), fmaxf(m2, m3));
            float S = psum[tid] * __expf(m0 - M) + psum[128 + tid] * __expf(m1 - M)
                    + psum[256 + tid] * __expf(m2 - M) + psum[384 + tid] * __expf(m3 - M);
            float l = M + __logf(S);
            float u = 0.7978845608028654f * (l + 0.044715f * l * l * l);
            gsh[tid] = 0.5f * l * (1.0f + tanhf(u));
        }
        __syncthreads();

        // ---- residual: out = gelu(lse) + x (x from fp16 A tile) ----
        {
            float* op = out + (size_t)t * (BM * KDIM);
#pragma unroll
            for (int i = 0; i < 16; i++) {
                int e = i * 2048 + tid * 4;
                int r = e >> 8, c = e & 255;
                uint32_t addr = sb + OFF_A + sw_off(r, c);
                uint32_t u0, u1;
                asm volatile("ld.shared.v2.b32 {%0,%1}, [%2];" : "=r"(u0), "=r"(u1) : "r"(addr));
                __half2 p0 = *(__half2*)&u0;
                __half2 p1 = *(__half2*)&u1;
                float gv = gsh[r];
                float4 o;
                o.x = __low2float(p0) + gv;
                o.y = __high2float(p0) + gv;
                o.z = __low2float(p1) + gv;
                o.w = __high2float(p1) + gv;
                __stcs((float4*)(op + e), o);
            }
        }
        __syncthreads();  // everyone done reading A(t)

        // ---- stage A(t+1) ----
        if (hn) {
#pragma unroll
            for (int i = 0; i < 16; i++) {
                int e = i * 2048 + tid * 4;
                uint32_t addr = sb + OFF_A + sw_off(e >> 8, e & 255);
                asm volatile("st.shared.v2.b32 [%0], {%1,%2};"
                             :: "r"(addr), "r"(h2[2 * i]), "r"(h2[2 * i + 1]));
            }
        }
    }
}

extern "C" void kernel_launch(void* const* d_in, const int* in_sizes, int n_in,
                              void* d_out, int out_size) {
    const float* x    = (const float*)d_in[0];
    const float* w    = (const float*)d_in[1];
    const float* bias = (const float*)d_in[2];
    const float* sub  = (const float*)d_in[3];
    float* out = (float*)d_out;

    cudaFuncSetAttribute(fused_gemm_lse_gelu_kernel,
                         cudaFuncAttributeMaxDynamicSharedMemorySize, SMEM_TOTAL);
    fused_gemm_lse_gelu_kernel<<<GRIDSZ, THREADS, SMEM_TOTAL>>>(x, w, bias, sub, out);
}